// round 7
// baseline (speedup 1.0000x reference)
#include <cuda_runtime.h>
#include <cstdint>

#define IN_F   784
#define KP1    832          // 784 padded to multiple of 64
#define HID    1024
#define OUT_F  10
#define N2P    16           // W2 rows padded 10 -> 16
#define B_MAX  16384

// ---------------- device scratch (allowed: __device__ globals) ----------------
__device__ __align__(16) int8_t  g_A  [B_MAX * KP1];   // ternary x, padded K
__device__ __align__(16) int8_t  g_W1q[HID   * KP1];   // ternary W1, padded K
__device__ __align__(16) int8_t  g_W2q[N2P   * HID];   // ternary W2, padded N
__device__ __align__(16) short   g_C1 [B_MAX * HID];   // GEMM1 out (|v|<=784)
__device__ __align__(16) int8_t  g_A2 [B_MAX * HID];   // ternary hidden acts
__device__ __align__(16) short   g_C2 [B_MAX * N2P];   // GEMM2 out (|v|<=1024)
__device__ __align__(16) int8_t  g_T2 [B_MAX * OUT_F]; // ternary logits

__device__ int                g_sum1[HID];
__device__ unsigned long long g_sq1 [HID];
__device__ float              g_a1[HID], g_b1[HID];    // fused BN1 scale/shift
__device__ int                g_sum2[N2P];
__device__ unsigned long long g_sq2 [N2P];
__device__ int                g_sum3, g_sq3n;

// ---------------- helpers ----------------
__device__ __forceinline__ float ternf(float v) {
    return fminf(1.f, fmaxf(-1.f, rintf(v)));   // round-half-even == jnp.round
}

#define MMA_S8(d, a, b)                                                        \
    asm volatile("mma.sync.aligned.m16n8k32.row.col.s32.s8.s8.s32 "            \
        "{%0,%1,%2,%3}, {%4,%5,%6,%7}, {%8,%9}, {%0,%1,%2,%3};"                \
        : "+r"((d)[0]), "+r"((d)[1]), "+r"((d)[2]), "+r"((d)[3])               \
        : "r"((a)[0]), "r"((a)[1]), "r"((a)[2]), "r"((a)[3]),                  \
          "r"((b)[0]), "r"((b)[1]))

__device__ __forceinline__ void cp16(void* smem_dst, const void* gsrc) {
    uint32_t d = (uint32_t)__cvta_generic_to_shared(smem_dst);
    asm volatile("cp.async.cg.shared.global [%0], [%1], 16;" :: "r"(d), "l"(gsrc));
}

// ---------------- init / quantize ----------------
__global__ void k_init() {
    int t = threadIdx.x;             // 1024 threads
    g_sum1[t] = 0; g_sq1[t] = 0ULL;
    if (t < N2P) { g_sum2[t] = 0; g_sq2[t] = 0ULL; }
    if (t == 0)  { g_sum3 = 0; g_sq3n = 0; }
}

__global__ void k_quant_x(const float* __restrict__ x, int Bsz) {
    int idx = blockIdx.x * blockDim.x + threadIdx.x;
    if (idx >= Bsz * KP1) return;
    int row = idx / KP1;
    int col = idx - row * KP1;
    int8_t v = 0;
    if (col < IN_F) {
        float h = 2.0f * x[row * IN_F + col] - 1.0f;   // exact in fp32
        v = (int8_t)ternf(h);
    }
    g_A[idx] = v;
}

__global__ void k_quant_w1(const float* __restrict__ W1) {
    int idx = blockIdx.x * blockDim.x + threadIdx.x;
    if (idx >= HID * KP1) return;
    int row = idx / KP1;
    int col = idx - row * KP1;
    int8_t v = 0;
    if (col < IN_F) v = (int8_t)ternf(W1[row * IN_F + col]);
    g_W1q[idx] = v;
}

__global__ void k_quant_w2(const float* __restrict__ W2) {
    int idx = blockIdx.x * blockDim.x + threadIdx.x;
    if (idx >= N2P * HID) return;
    int row = idx >> 10;
    int col = idx & (HID - 1);
    int8_t v = 0;
    if (row < OUT_F) v = (int8_t)ternf(W2[row * HID + col]);
    g_W2q[idx] = v;
}

// ---------------- GEMM1: [B,832] x [1024,832]^T -> C1 int16 ----------------
// Block 128x128, BK=64, 2-stage cp.async pipeline, 8 warps of 64x32.
// smem rows padded to 80B: word index 20*r + q -> all 32 banks distinct.
__device__ __forceinline__ void g1_load(int8_t* sA, int8_t* sB,
                                        int tid, int bm0, int bn0, int kt) {
    int k0 = kt * 64;
    #pragma unroll
    for (int i = 0; i < 2; i++) {
        int v  = tid + i * 256;
        int r  = v >> 2;
        int cv = (v & 3) * 16;
        cp16(sA + r * 80 + cv, g_A   + (size_t)(bm0 + r) * KP1 + k0 + cv);
        cp16(sB + r * 80 + cv, g_W1q + (size_t)(bn0 + r) * KP1 + k0 + cv);
    }
    asm volatile("cp.async.commit_group;" ::: "memory");
}

__global__ __launch_bounds__(256, 2) void k_gemm1(int Bsz) {
    __shared__ __align__(16) int8_t sA[2][128 * 80];
    __shared__ __align__(16) int8_t sB[2][128 * 80];

    const int tid  = threadIdx.x;
    const int bm0  = blockIdx.y * 128;
    const int bn0  = blockIdx.x * 128;
    const int warp = tid >> 5, lane = tid & 31;
    const int g = lane >> 2, q = lane & 3;
    const int wr = warp >> 2, wc = warp & 3;   // 2 x 4 warps

    int acc[4][4][4];
    #pragma unroll
    for (int mt = 0; mt < 4; mt++)
        #pragma unroll
        for (int nt = 0; nt < 4; nt++)
            #pragma unroll
            for (int i = 0; i < 4; i++) acc[mt][nt][i] = 0;

    const int KT = KP1 / 64;   // 13
    g1_load(sA[0], sB[0], tid, bm0, bn0, 0);

    for (int kt = 0; kt < KT; kt++) {
        int cur = kt & 1;
        if (kt + 1 < KT) {
            g1_load(sA[cur ^ 1], sB[cur ^ 1], tid, bm0, bn0, kt + 1);
            asm volatile("cp.async.wait_group 1;" ::: "memory");
        } else {
            asm volatile("cp.async.wait_group 0;" ::: "memory");
        }
        __syncthreads();

        #pragma unroll
        for (int s = 0; s < 2; s++) {
            uint32_t a[4][4], b[4][2];
            #pragma unroll
            for (int mt = 0; mt < 4; mt++) {
                const int8_t* p = &sA[cur][(wr * 64 + mt * 16 + g) * 80 + s * 32 + q * 4];
                a[mt][0] = *(const uint32_t*)(p);
                a[mt][1] = *(const uint32_t*)(p + 8 * 80);
                a[mt][2] = *(const uint32_t*)(p + 16);
                a[mt][3] = *(const uint32_t*)(p + 8 * 80 + 16);
            }
            #pragma unroll
            for (int nt = 0; nt < 4; nt++) {
                const int8_t* p = &sB[cur][(wc * 32 + nt * 8 + g) * 80 + s * 32 + q * 4];
                b[nt][0] = *(const uint32_t*)(p);
                b[nt][1] = *(const uint32_t*)(p + 16);
            }
            #pragma unroll
            for (int mt = 0; mt < 4; mt++)
                #pragma unroll
                for (int nt = 0; nt < 4; nt++)
                    MMA_S8(acc[mt][nt], a[mt], b[nt]);
        }
        __syncthreads();
    }

    // epilogue: int16 store
    #pragma unroll
    for (int mt = 0; mt < 4; mt++) {
        int row0 = bm0 + wr * 64 + mt * 16 + g;
        #pragma unroll
        for (int nt = 0; nt < 4; nt++) {
            int col = bn0 + wc * 32 + nt * 8 + q * 2;
            short2 lo = make_short2((short)acc[mt][nt][0], (short)acc[mt][nt][1]);
            short2 hi = make_short2((short)acc[mt][nt][2], (short)acc[mt][nt][3]);
            *(short2*)&g_C1[(size_t)row0       * HID + col] = lo;
            *(short2*)&g_C1[(size_t)(row0 + 8) * HID + col] = hi;
        }
    }
}

// ---------------- BN1 stats (exact integer, deterministic) ----------------
__global__ void k_stats1(int Bsz) {
    int t  = threadIdx.x;
    int r0 = blockIdx.x * 128;
    int sum[4] = {0, 0, 0, 0};
    int sq [4] = {0, 0, 0, 0};      // max 784^2*128 = 7.9e7 < 2^31
    for (int r = 0; r < 128; r++) {
        const short* row = &g_C1[(size_t)(r0 + r) * HID];
        #pragma unroll
        for (int j = 0; j < 4; j++) {
            int v = row[t + j * 256];
            sum[j] += v; sq[j] += v * v;
        }
    }
    #pragma unroll
    for (int j = 0; j < 4; j++) {
        atomicAdd(&g_sum1[t + j * 256], sum[j]);
        atomicAdd(&g_sq1 [t + j * 256], (unsigned long long)(unsigned int)sq[j]);
    }
}

__global__ void k_coef1(const float* __restrict__ gamma1,
                        const float* __restrict__ beta1, int Bsz) {
    int f = threadIdx.x;            // 1024 threads
    double mean = (double)g_sum1[f] / (double)Bsz;
    double var  = (double)g_sq1[f] / (double)Bsz - mean * mean;   // biased
    double rstd = 1.0 / sqrt(var + 1e-5);
    double ga = (double)gamma1[f];
    g_a1[f] = (float)(rstd * ga);
    g_b1[f] = (float)((double)beta1[f] - mean * rstd * ga);
}

// ---------------- normalize + ternary -> int8 hidden acts ----------------
__global__ void k_act1(int Bsz) {
    int idx = (blockIdx.x * blockDim.x + threadIdx.x) * 4;
    if (idx >= Bsz * HID) return;
    int f0 = idx & (HID - 1);
    int2 raw = *(const int2*)&g_C1[idx];        // 4 int16
    const short* pv = (const short*)&raw;
    char4 o;
    o.x = (int8_t)ternf(fmaf((float)pv[0], g_a1[f0 + 0], g_b1[f0 + 0]));
    o.y = (int8_t)ternf(fmaf((float)pv[1], g_a1[f0 + 1], g_b1[f0 + 1]));
    o.z = (int8_t)ternf(fmaf((float)pv[2], g_a1[f0 + 2], g_b1[f0 + 2]));
    o.w = (int8_t)ternf(fmaf((float)pv[3], g_a1[f0 + 3], g_b1[f0 + 3]));
    *(char4*)&g_A2[idx] = o;
}

// ---------------- GEMM2: [B,1024] x [16,1024]^T -> C2 int16 ----------------
__global__ __launch_bounds__(256, 2) void k_gemm2(int Bsz) {
    __shared__ __align__(16) int8_t sA[2][128 * 80];
    __shared__ __align__(16) int8_t sB[16 * 1040];   // padded stride 1040

    const int tid  = threadIdx.x;
    const int bm0  = blockIdx.x * 128;
    const int warp = tid >> 5, lane = tid & 31;
    const int g = lane >> 2, q = lane & 3;

    // resident B2 (16KB), plain vector loads
    #pragma unroll
    for (int i = 0; i < 4; i++) {
        int v  = tid + i * 256;
        int r  = v >> 6;
        int cv = (v & 63) * 16;
        *(int4*)&sB[r * 1040 + cv] = *(const int4*)&g_W2q[r * HID + cv];
    }

    int acc[2][4];
    #pragma unroll
    for (int nt = 0; nt < 2; nt++)
        #pragma unroll
        for (int i = 0; i < 4; i++) acc[nt][i] = 0;

    const int KT = HID / 64;   // 16
    // prologue load of A stage 0
    #pragma unroll
    for (int i = 0; i < 2; i++) {
        int v = tid + i * 256; int r = v >> 2; int cv = (v & 3) * 16;
        cp16(&sA[0][r * 80 + cv], g_A2 + (size_t)(bm0 + r) * HID + cv);
    }
    asm volatile("cp.async.commit_group;" ::: "memory");

    for (int kt = 0; kt < KT; kt++) {
        int cur = kt & 1;
        if (kt + 1 < KT) {
            #pragma unroll
            for (int i = 0; i < 2; i++) {
                int v = tid + i * 256; int r = v >> 2; int cv = (v & 3) * 16;
                cp16(&sA[cur ^ 1][r * 80 + cv],
                     g_A2 + (size_t)(bm0 + r) * HID + (kt + 1) * 64 + cv);
            }
            asm volatile("cp.async.commit_group;" ::: "memory");
            asm volatile("cp.async.wait_group 1;" ::: "memory");
        } else {
            asm volatile("cp.async.wait_group 0;" ::: "memory");
        }
        __syncthreads();

        #pragma unroll
        for (int s = 0; s < 2; s++) {
            uint32_t a[4], b[2][2];
            const int8_t* pa = &sA[cur][(warp * 16 + g) * 80 + s * 32 + q * 4];
            a[0] = *(const uint32_t*)(pa);
            a[1] = *(const uint32_t*)(pa + 8 * 80);
            a[2] = *(const uint32_t*)(pa + 16);
            a[3] = *(const uint32_t*)(pa + 8 * 80 + 16);
            #pragma unroll
            for (int nt = 0; nt < 2; nt++) {
                const int8_t* pb = &sB[(nt * 8 + g) * 1040 + kt * 64 + s * 32 + q * 4];
                b[nt][0] = *(const uint32_t*)(pb);
                b[nt][1] = *(const uint32_t*)(pb + 16);
            }
            MMA_S8(acc[0], a, b[0]);
            MMA_S8(acc[1], a, b[1]);
        }
        __syncthreads();
    }

    int row0 = bm0 + warp * 16 + g;
    #pragma unroll
    for (int nt = 0; nt < 2; nt++) {
        int col = nt * 8 + q * 2;
        short2 lo = make_short2((short)acc[nt][0], (short)acc[nt][1]);
        short2 hi = make_short2((short)acc[nt][2], (short)acc[nt][3]);
        *(short2*)&g_C2[(size_t)row0       * N2P + col] = lo;
        *(short2*)&g_C2[(size_t)(row0 + 8) * N2P + col] = hi;
    }
}

// ---------------- BN2 stats ----------------
__global__ void k_stats2(int Bsz) {
    int t   = threadIdx.x;
    int col = t & 15;
    int rg  = t >> 4;
    int r0  = blockIdx.x * 256;
    int sum = 0, sq = 0;                       // sq <= 16*1024^2 = 1.7e7
    #pragma unroll
    for (int k = 0; k < 16; k++) {
        int v = g_C2[(size_t)(r0 + rg + k * 16) * N2P + col];
        sum += v; sq += v * v;
    }
    atomicAdd(&g_sum2[col], sum);
    atomicAdd(&g_sq2 [col], (unsigned long long)(unsigned int)sq);
}

// ---------------- BN2 normalize + ternary + tensornorm stats ----------------
__global__ void k_act2(const float* __restrict__ gamma2,
                       const float* __restrict__ beta2, int Bsz) {
    int idx   = blockIdx.x * blockDim.x + threadIdx.x;
    int total = Bsz * OUT_F;
    int s = 0, s2 = 0;
    if (idx < total) {
        int row = idx / OUT_F;
        int col = idx - row * OUT_F;
        int c = g_C2[(size_t)row * N2P + col];
        double mean = (double)g_sum2[col] / (double)Bsz;
        double var  = (double)g_sq2[col] / (double)Bsz - mean * mean;
        double rstd = 1.0 / sqrt(var + 1e-5);
        double z = ((double)c - mean) * rstd * (double)gamma2[col] + (double)beta2[col];
        int ti = (int)fmin(1.0, fmax(-1.0, rint(z)));
        g_T2[idx] = (int8_t)ti;
        s = ti; s2 = ti * ti;
    }
    #pragma unroll
    for (int o = 16; o > 0; o >>= 1) {
        s  += __shfl_xor_sync(0xffffffffu, s,  o);
        s2 += __shfl_xor_sync(0xffffffffu, s2, o);
    }
    if ((threadIdx.x & 31) == 0) {
        atomicAdd(&g_sum3, s);
        atomicAdd(&g_sq3n, s2);
    }
}

// ---------------- TensorNorm (unbiased var, eps=1e-4) ----------------
__global__ void k_final(const float* __restrict__ tn_w,
                        const float* __restrict__ tn_b,
                        float* __restrict__ out, int Bsz) {
    int idx   = blockIdx.x * blockDim.x + threadIdx.x;
    int total = Bsz * OUT_F;
    if (idx >= total) return;
    double N = (double)total;
    double S = (double)g_sum3;
    double m = S / N;
    double var = ((double)g_sq3n - S * S / N) / (N - 1.0);
    double r = 1.0 / sqrt(var + 1e-4);
    out[idx] = (float)(((double)g_T2[idx] - m) * r * (double)tn_w[0] + (double)tn_b[0]);
}

// ---------------- launcher ----------------
extern "C" void kernel_launch(void* const* d_in, const int* in_sizes, int n_in,
                              void* d_out, int out_size) {
    const float* x      = (const float*)d_in[0];
    const float* W1     = (const float*)d_in[1];
    const float* gamma1 = (const float*)d_in[2];
    const float* beta1  = (const float*)d_in[3];
    const float* W2     = (const float*)d_in[4];
    const float* gamma2 = (const float*)d_in[5];
    const float* beta2  = (const float*)d_in[6];
    const float* tn_w   = (const float*)d_in[7];
    const float* tn_b   = (const float*)d_in[8];
    float* out = (float*)d_out;

    int Bsz = in_sizes[0] / IN_F;   // 16384

    k_init<<<1, 1024>>>();
    k_quant_x <<<(Bsz * KP1 + 255) / 256, 256>>>(x, Bsz);
    k_quant_w1<<<(HID * KP1 + 255) / 256, 256>>>(W1);
    k_quant_w2<<<(N2P * HID + 255) / 256, 256>>>(W2);

    dim3 g1(HID / 128, Bsz / 128);
    k_gemm1<<<g1, 256>>>(Bsz);

    k_stats1<<<Bsz / 128, 256>>>(Bsz);
    k_coef1 <<<1, 1024>>>(gamma1, beta1, Bsz);
    k_act1  <<<(Bsz * HID / 4 + 255) / 256, 256>>>(Bsz);

    k_gemm2<<<Bsz / 128, 256>>>(Bsz);

    k_stats2<<<Bsz / 256, 256>>>(Bsz);
    k_act2  <<<(Bsz * OUT_F + 255) / 256, 256>>>(gamma2, beta2, Bsz);
    k_final <<<(Bsz * OUT_F + 255) / 256, 256>>>(tn_w, tn_b, out, Bsz);
}

// round 9
// speedup vs baseline: 1.0894x; 1.0894x over previous
#include <cuda_runtime.h>
#include <cstdint>

#define IN_F   784
#define KP1    832          // 784 padded to multiple of 64
#define HID    1024
#define OUT_F  10
#define N2P    16
#define B_MAX  16384

// ---------------- device scratch ----------------
__device__ __align__(16) int8_t  g_A  [B_MAX * KP1];
__device__ __align__(16) int8_t  g_W1q[HID   * KP1];
__device__ __align__(16) int8_t  g_W2q[N2P   * HID];
__device__ __align__(16) short   g_C1 [B_MAX * HID];
__device__ __align__(16) short   g_C2 [B_MAX * N2P];
__device__ __align__(16) int8_t  g_T2 [B_MAX * OUT_F];

__device__ int                g_sum1[HID];
__device__ unsigned long long g_sq1 [HID];
__device__ __align__(16) float g_a1[HID];
__device__ __align__(16) float g_b1[HID];
__device__ int                g_sum2[N2P];
__device__ unsigned long long g_sq2 [N2P];
__device__ int                g_sum3, g_sq3n;

// ---------------- helpers ----------------
__device__ __forceinline__ float ternf(float v) {
    return fminf(1.f, fmaxf(-1.f, rintf(v)));
}

__device__ __forceinline__ uint32_t smem_u32(const void* p) {
    uint32_t a;
    asm("{ .reg .u64 t; cvta.to.shared.u64 t, %1; cvt.u32.u64 %0, t; }" : "=r"(a) : "l"(p));
    return a;
}

#define MMA_S8(d, a, b)                                                        \
    asm volatile("mma.sync.aligned.m16n8k32.row.col.s32.s8.s8.s32 "            \
        "{%0,%1,%2,%3}, {%4,%5,%6,%7}, {%8,%9}, {%0,%1,%2,%3};"                \
        : "+r"((d)[0]), "+r"((d)[1]), "+r"((d)[2]), "+r"((d)[3])               \
        : "r"((a)[0]), "r"((a)[1]), "r"((a)[2]), "r"((a)[3]),                  \
          "r"((b)[0]), "r"((b)[1]))

#define LDSM4(r0, r1, r2, r3, addr)                                            \
    asm volatile("ldmatrix.sync.aligned.m8n8.x4.shared.b16 {%0,%1,%2,%3}, [%4];" \
        : "=r"(r0), "=r"(r1), "=r"(r2), "=r"(r3) : "r"(addr))

__device__ __forceinline__ void cp16(uint32_t smem_dst, const void* gsrc) {
    asm volatile("cp.async.cg.shared.global [%0], [%1], 16;" :: "r"(smem_dst), "l"(gsrc));
}
#define CP_COMMIT() asm volatile("cp.async.commit_group;" ::: "memory")
#define CP_WAIT(n)  asm volatile("cp.async.wait_group %0;" :: "n"(n) : "memory")

// ---------------- init / quantize ----------------
__global__ void k_init() {
    int t = threadIdx.x;
    g_sum1[t] = 0; g_sq1[t] = 0ULL;
    if (t < N2P) { g_sum2[t] = 0; g_sq2[t] = 0ULL; }
    if (t == 0)  { g_sum3 = 0; g_sq3n = 0; }
}

__global__ void k_quant_x(const float* __restrict__ x, int Bsz) {
    int idx = blockIdx.x * blockDim.x + threadIdx.x;
    if (idx >= Bsz * KP1) return;
    int row = idx / KP1;
    int col = idx - row * KP1;
    int8_t v = 0;
    if (col < IN_F) {
        float h = 2.0f * x[row * IN_F + col] - 1.0f;
        v = (int8_t)ternf(h);
    }
    g_A[idx] = v;
}

__global__ void k_quant_w1(const float* __restrict__ W1) {
    int idx = blockIdx.x * blockDim.x + threadIdx.x;
    if (idx >= HID * KP1) return;
    int row = idx / KP1;
    int col = idx - row * KP1;
    int8_t v = 0;
    if (col < IN_F) v = (int8_t)ternf(W1[row * IN_F + col]);
    g_W1q[idx] = v;
}

__global__ void k_quant_w2(const float* __restrict__ W2) {
    int idx = blockIdx.x * blockDim.x + threadIdx.x;
    if (idx >= N2P * HID) return;
    int row = idx >> 10;
    int col = idx & (HID - 1);
    int8_t v = 0;
    if (row < OUT_F) v = (int8_t)ternf(W2[row * HID + col]);
    g_W2q[idx] = v;
}

// ============ GEMM1: [B,832] x [1024,832]^T -> C1 int16 + fused BN1 stats ============
// Block 128x128, BK=64, 4-stage cp.async, ldmatrix operand loads, 8 warps (2x4) of 64x32.
#define G1_STG   4
#define G1_ASZ   (128 * 80)         // one stage of A (or B): 10240 B
#define G1_BOFF  (G1_STG * G1_ASZ)  // 40960
#define G1_SMEM  (2 * G1_STG * G1_ASZ)  // 81920
#define G1_KT    (KP1 / 64)         // 13

__device__ __forceinline__ void g1_load(uint32_t sb, int tid, int bm0, int bn0, int kt) {
    int stage = kt & 3;
    int k0 = kt * 64;
    #pragma unroll
    for (int i = 0; i < 2; i++) {
        int v = tid + i * 256;
        int r = v >> 2, c = (v & 3) * 16;
        cp16(sb + stage * G1_ASZ + r * 80 + c,
             g_A + (size_t)(bm0 + r) * KP1 + k0 + c);
        cp16(sb + G1_BOFF + stage * G1_ASZ + r * 80 + c,
             g_W1q + (size_t)(bn0 + r) * KP1 + k0 + c);
    }
    CP_COMMIT();
}

__global__ void __launch_bounds__(256, 2) k_gemm1(int Bsz) {
    extern __shared__ __align__(16) char smem[];
    const uint32_t sb = smem_u32(smem);
    const int tid = threadIdx.x, warp = tid >> 5, lane = tid & 31;
    const int bm0 = blockIdx.y * 128;
    const int bn0 = blockIdx.x * 128;
    const int wr = warp >> 2, wc = warp & 3;

    // ldmatrix per-lane base offsets (within a stage)
    const int lr = lane & 7;
    uint32_t abase[4], bbase[2];
    #pragma unroll
    for (int mt = 0; mt < 4; mt++)
        abase[mt] = (uint32_t)((wr * 64 + mt * 16 + ((lane >> 3) & 1) * 8 + lr) * 80
                               + (lane >> 4) * 16);
    #pragma unroll
    for (int np = 0; np < 2; np++)
        bbase[np] = (uint32_t)((wc * 32 + np * 16 + (lane >> 4) * 8 + lr) * 80
                               + ((lane >> 3) & 1) * 16);

    int acc[4][4][4];
    #pragma unroll
    for (int mt = 0; mt < 4; mt++)
        #pragma unroll
        for (int nt = 0; nt < 4; nt++)
            #pragma unroll
            for (int i = 0; i < 4; i++) acc[mt][nt][i] = 0;

    g1_load(sb, tid, bm0, bn0, 0);
    g1_load(sb, tid, bm0, bn0, 1);
    g1_load(sb, tid, bm0, bn0, 2);

    for (int kt = 0; kt < G1_KT; kt++) {
        if (kt < G1_KT - 2)      CP_WAIT(2);
        else if (kt < G1_KT - 1) CP_WAIT(1);
        else                     CP_WAIT(0);
        __syncthreads();
        if (kt + 3 < G1_KT) g1_load(sb, tid, bm0, bn0, kt + 3);

        const uint32_t sa = sb + (kt & 3) * G1_ASZ;
        const uint32_t sbb = sb + G1_BOFF + (kt & 3) * G1_ASZ;
        #pragma unroll
        for (int s = 0; s < 2; s++) {
            uint32_t a[4][4], b[4][2];
            #pragma unroll
            for (int mt = 0; mt < 4; mt++)
                LDSM4(a[mt][0], a[mt][1], a[mt][2], a[mt][3], sa + abase[mt] + s * 32);
            LDSM4(b[0][0], b[0][1], b[1][0], b[1][1], sbb + bbase[0] + s * 32);
            LDSM4(b[2][0], b[2][1], b[3][0], b[3][1], sbb + bbase[1] + s * 32);
            #pragma unroll
            for (int mt = 0; mt < 4; mt++)
                #pragma unroll
                for (int nt = 0; nt < 4; nt++)
                    MMA_S8(acc[mt][nt], a[mt], b[nt]);
        }
    }

    // ---- store C1 (int16) ----
    const int g = lane >> 2, q = lane & 3;
    #pragma unroll
    for (int mt = 0; mt < 4; mt++) {
        int row0 = bm0 + wr * 64 + mt * 16 + g;
        #pragma unroll
        for (int nt = 0; nt < 4; nt++) {
            int col = bn0 + wc * 32 + nt * 8 + q * 2;
            short2 lo = make_short2((short)acc[mt][nt][0], (short)acc[mt][nt][1]);
            short2 hi = make_short2((short)acc[mt][nt][2], (short)acc[mt][nt][3]);
            *(short2*)&g_C1[(size_t)row0       * HID + col] = lo;
            *(short2*)&g_C1[(size_t)(row0 + 8) * HID + col] = hi;
        }
    }

    // ---- fused BN1 stats from registers ----
    int sums[8], sqs[8];
    #pragma unroll
    for (int nt = 0; nt < 4; nt++)
        #pragma unroll
        for (int c = 0; c < 2; c++) {
            int s_ = 0, q_ = 0;
            #pragma unroll
            for (int mt = 0; mt < 4; mt++) {
                int v1 = acc[mt][nt][c], v2 = acc[mt][nt][c + 2];
                s_ += v1 + v2; q_ += v1 * v1 + v2 * v2;
            }
            sums[nt * 2 + c] = s_; sqs[nt * 2 + c] = q_;
        }
    #pragma unroll
    for (int m = 4; m <= 16; m <<= 1)
        #pragma unroll
        for (int i = 0; i < 8; i++) {
            sums[i] += __shfl_xor_sync(0xffffffffu, sums[i], m);
            sqs[i]  += __shfl_xor_sync(0xffffffffu, sqs[i],  m);
        }
    if (lane < 4) {
        #pragma unroll
        for (int nt = 0; nt < 4; nt++)
            #pragma unroll
            for (int c = 0; c < 2; c++) {
                int col = bn0 + wc * 32 + nt * 8 + lane * 2 + c;
                atomicAdd(&g_sum1[col], sums[nt * 2 + c]);
                atomicAdd(&g_sq1[col],
                          (unsigned long long)(unsigned int)sqs[nt * 2 + c]);
            }
    }
}

// ---------------- BN1 coefs ----------------
__global__ void k_coef1(const float* __restrict__ gamma1,
                        const float* __restrict__ beta1, int Bsz) {
    int f = threadIdx.x;
    double mean = (double)g_sum1[f] / (double)Bsz;
    double var  = (double)g_sq1[f] / (double)Bsz - mean * mean;
    double rstd = 1.0 / sqrt(var + 1e-5);
    double ga = (double)gamma1[f];
    g_a1[f] = (float)(rstd * ga);
    g_b1[f] = (float)((double)beta1[f] - mean * rstd * ga);
}

// ============ GEMM2: fused BN1-normalize + ternary + [B,1024] x [16,1024]^T ============
// A source is C1 (int16); convert to s8 fragments in registers (no extra sync).
#define G2_STG    3
#define G2_RSZ    (128 * 144)                 // one raw stage: 18432 B
#define G2_B2OFF  (G2_STG * G2_RSZ)           // 55296
#define G2_CAOFF  (G2_B2OFF + 16 * 1040)      // 71936
#define G2_CBOFF  (G2_CAOFF + 4096)           // 76032
#define G2_SMEM   (G2_CBOFF + 4096)           // 80128
#define G2_KT     (HID / 64)                  // 16

__device__ __forceinline__ void g2_load(uint32_t sb, int tid, int bm0, int kt) {
    int stage = kt % 3;
    #pragma unroll
    for (int i = 0; i < 4; i++) {
        int v = tid + i * 256;
        int r = v >> 3, c = (v & 7) * 16;
        cp16(sb + stage * G2_RSZ + r * 144 + c,
             (const char*)g_C1 + (size_t)(bm0 + r) * 2048 + kt * 128 + c);
    }
    CP_COMMIT();
}

__global__ void __launch_bounds__(256, 2) k_gemm2(int Bsz) {
    extern __shared__ __align__(16) char smem[];
    const uint32_t sb = smem_u32(smem);
    char*  smc = smem;
    float* sCa = (float*)(smem + G2_CAOFF);
    float* sCb = (float*)(smem + G2_CBOFF);
    int8_t* sB2 = (int8_t*)(smem + G2_B2OFF);

    const int tid = threadIdx.x, warp = tid >> 5, lane = tid & 31;
    const int g = lane >> 2, q = lane & 3;
    const int bm0 = blockIdx.x * 128;

    // resident W2q (16 x 1024, padded stride 1040) + BN1 coefs
    #pragma unroll
    for (int i = 0; i < 4; i++) {
        int v = tid + i * 256;
        int r = v >> 6, c = (v & 63) * 16;
        *(int4*)&sB2[r * 1040 + c] = *(const int4*)&g_W2q[r * HID + c];
    }
    ((float4*)sCa)[tid] = ((const float4*)g_a1)[tid];
    ((float4*)sCb)[tid] = ((const float4*)g_b1)[tid];

    int acc[2][4];
    #pragma unroll
    for (int nt = 0; nt < 2; nt++)
        #pragma unroll
        for (int i = 0; i < 4; i++) acc[nt][i] = 0;

    g2_load(sb, tid, bm0, 0);
    g2_load(sb, tid, bm0, 1);

    for (int kt = 0; kt < G2_KT; kt++) {
        if (kt < G2_KT - 1) CP_WAIT(1);
        else                CP_WAIT(0);
        __syncthreads();
        if (kt + 2 < G2_KT) g2_load(sb, tid, bm0, kt + 2);

        const int stage = kt % 3;
        #pragma unroll
        for (int s = 0; s < 2; s++) {
            uint32_t a[4];
            #pragma unroll
            for (int c16 = 0; c16 < 2; c16++)
                #pragma unroll
                for (int h = 0; h < 2; h++) {
                    int row = warp * 16 + g + h * 8;
                    short4 v = *(const short4*)(smc + stage * G2_RSZ + row * 144
                                                + s * 64 + c16 * 32 + q * 8);
                    int f = kt * 64 + s * 32 + c16 * 16 + q * 4;
                    int i0 = (int)ternf(fmaf((float)v.x, sCa[f + 0], sCb[f + 0]));
                    int i1 = (int)ternf(fmaf((float)v.y, sCa[f + 1], sCb[f + 1]));
                    int i2 = (int)ternf(fmaf((float)v.z, sCa[f + 2], sCb[f + 2]));
                    int i3 = (int)ternf(fmaf((float)v.w, sCa[f + 3], sCb[f + 3]));
                    a[h + 2 * c16] = (uint32_t)(uint8_t)i0
                                   | ((uint32_t)(uint8_t)i1 << 8)
                                   | ((uint32_t)(uint8_t)i2 << 16)
                                   | ((uint32_t)(uint8_t)i3 << 24);
                }
            #pragma unroll
            for (int nt = 0; nt < 2; nt++) {
                uint32_t b[2];
                const int8_t* pb = &sB2[(nt * 8 + g) * 1040 + kt * 64 + s * 32 + q * 4];
                b[0] = *(const uint32_t*)(pb);
                b[1] = *(const uint32_t*)(pb + 16);
                MMA_S8(acc[nt], a, b);
            }
        }
    }

    int row0 = bm0 + warp * 16 + g;
    #pragma unroll
    for (int nt = 0; nt < 2; nt++) {
        int col = nt * 8 + q * 2;
        short2 lo = make_short2((short)acc[nt][0], (short)acc[nt][1]);
        short2 hi = make_short2((short)acc[nt][2], (short)acc[nt][3]);
        *(short2*)&g_C2[(size_t)row0       * N2P + col] = lo;
        *(short2*)&g_C2[(size_t)(row0 + 8) * N2P + col] = hi;
    }
}

// ---------------- BN2 stats ----------------
__global__ void k_stats2(int Bsz) {
    int t   = threadIdx.x;
    int col = t & 15;
    int rg  = t >> 4;
    int r0  = blockIdx.x * 256;
    int sum = 0, sq = 0;
    #pragma unroll
    for (int k = 0; k < 16; k++) {
        int v = g_C2[(size_t)(r0 + rg + k * 16) * N2P + col];
        sum += v; sq += v * v;
    }
    atomicAdd(&g_sum2[col], sum);
    atomicAdd(&g_sq2[col], (unsigned long long)(unsigned int)sq);
}

// ---------------- BN2 normalize + ternary + tensornorm stats ----------------
__global__ void k_act2(const float* __restrict__ gamma2,
                       const float* __restrict__ beta2, int Bsz) {
    int idx   = blockIdx.x * blockDim.x + threadIdx.x;
    int total = Bsz * OUT_F;
    int s = 0, s2 = 0;
    if (idx < total) {
        int row = idx / OUT_F;
        int col = idx - row * OUT_F;
        int c = g_C2[(size_t)row * N2P + col];
        double mean = (double)g_sum2[col] / (double)Bsz;
        double var  = (double)g_sq2[col] / (double)Bsz - mean * mean;
        double rstd = 1.0 / sqrt(var + 1e-5);
        double z = ((double)c - mean) * rstd * (double)gamma2[col] + (double)beta2[col];
        int ti = (int)fmin(1.0, fmax(-1.0, rint(z)));
        g_T2[idx] = (int8_t)ti;
        s = ti; s2 = ti * ti;
    }
    #pragma unroll
    for (int o = 16; o > 0; o >>= 1) {
        s  += __shfl_xor_sync(0xffffffffu, s,  o);
        s2 += __shfl_xor_sync(0xffffffffu, s2, o);
    }
    if ((threadIdx.x & 31) == 0) {
        atomicAdd(&g_sum3, s);
        atomicAdd(&g_sq3n, s2);
    }
}

// ---------------- TensorNorm ----------------
__global__ void k_final(const float* __restrict__ tn_w,
                        const float* __restrict__ tn_b,
                        float* __restrict__ out, int Bsz) {
    int idx   = blockIdx.x * blockDim.x + threadIdx.x;
    int total = Bsz * OUT_F;
    if (idx >= total) return;
    double N = (double)total;
    double S = (double)g_sum3;
    double m = S / N;
    double var = ((double)g_sq3n - S * S / N) / (N - 1.0);
    double r = 1.0 / sqrt(var + 1e-4);
    out[idx] = (float)(((double)g_T2[idx] - m) * r * (double)tn_w[0] + (double)tn_b[0]);
}

// ---------------- launcher ----------------
extern "C" void kernel_launch(void* const* d_in, const int* in_sizes, int n_in,
                              void* d_out, int out_size) {
    const float* x      = (const float*)d_in[0];
    const float* W1     = (const float*)d_in[1];
    const float* gamma1 = (const float*)d_in[2];
    const float* beta1  = (const float*)d_in[3];
    const float* W2     = (const float*)d_in[4];
    const float* gamma2 = (const float*)d_in[5];
    const float* beta2  = (const float*)d_in[6];
    const float* tn_w   = (const float*)d_in[7];
    const float* tn_b   = (const float*)d_in[8];
    float* out = (float*)d_out;

    int Bsz = in_sizes[0] / IN_F;   // 16384

    static int attr_done = 0;
    if (!attr_done) {
        cudaFuncSetAttribute(k_gemm1, cudaFuncAttributeMaxDynamicSharedMemorySize, G1_SMEM);
        cudaFuncSetAttribute(k_gemm2, cudaFuncAttributeMaxDynamicSharedMemorySize, G2_SMEM);
        attr_done = 1;
    }

    k_init<<<1, 1024>>>();
    k_quant_x <<<(Bsz * KP1 + 255) / 256, 256>>>(x, Bsz);
    k_quant_w1<<<(HID * KP1 + 255) / 256, 256>>>(W1);
    k_quant_w2<<<(N2P * HID + 255) / 256, 256>>>(W2);

    dim3 g1(HID / 128, Bsz / 128);
    k_gemm1<<<g1, 256, G1_SMEM>>>(Bsz);            // fused BN1 stats

    k_coef1<<<1, 1024>>>(gamma1, beta1, Bsz);

    k_gemm2<<<Bsz / 128, 256, G2_SMEM>>>(Bsz);     // fused BN1-apply + ternary

    k_stats2<<<Bsz / 256, 256>>>(Bsz);
    k_act2  <<<(Bsz * OUT_F + 255) / 256, 256>>>(gamma2, beta2, Bsz);
    k_final <<<(Bsz * OUT_F + 255) / 256, 256>>>(tn_w, tn_b, out, Bsz);
}

// round 12
// speedup vs baseline: 1.1986x; 1.1002x over previous
#include <cuda_runtime.h>
#include <cstdint>

#define IN_F   784
#define KP1    832          // 784 padded to multiple of 64
#define HID    1024
#define OUT_F  10
#define N2P    16
#define B_MAX  16384

// ---------------- device scratch ----------------
__device__ __align__(16) int8_t  g_A  [B_MAX * KP1];
__device__ __align__(16) int8_t  g_W1q[HID   * KP1];
__device__ __align__(16) int8_t  g_W2q[N2P   * HID];
__device__ __align__(16) short   g_C1 [B_MAX * HID];
__device__ __align__(16) short   g_C2 [B_MAX * N2P];
__device__ __align__(16) int8_t  g_T2 [B_MAX * OUT_F];

__device__ int                g_sum1[HID];
__device__ unsigned long long g_sq1 [HID];
__device__ __align__(16) float g_a1[HID];
__device__ __align__(16) float g_b1[HID];
__device__ int                g_sum2[N2P];
__device__ unsigned long long g_sq2 [N2P];
__device__ int                g_sum3, g_sq3n;

// ---------------- helpers ----------------
__device__ __forceinline__ float ternf(float v) {
    return fminf(1.f, fmaxf(-1.f, rintf(v)));
}

__device__ __forceinline__ uint32_t smem_u32(const void* p) {
    uint32_t a;
    asm("{ .reg .u64 t; cvta.to.shared.u64 t, %1; cvt.u32.u64 %0, t; }" : "=r"(a) : "l"(p));
    return a;
}

#define MMA_S8(d, a, b)                                                        \
    asm volatile("mma.sync.aligned.m16n8k32.row.col.s32.s8.s8.s32 "            \
        "{%0,%1,%2,%3}, {%4,%5,%6,%7}, {%8,%9}, {%0,%1,%2,%3};"                \
        : "+r"((d)[0]), "+r"((d)[1]), "+r"((d)[2]), "+r"((d)[3])               \
        : "r"((a)[0]), "r"((a)[1]), "r"((a)[2]), "r"((a)[3]),                  \
          "r"((b)[0]), "r"((b)[1]))

#define LDSM4(r0, r1, r2, r3, addr)                                            \
    asm volatile("ldmatrix.sync.aligned.m8n8.x4.shared.b16 {%0,%1,%2,%3}, [%4];" \
        : "=r"(r0), "=r"(r1), "=r"(r2), "=r"(r3) : "r"(addr))

__device__ __forceinline__ void cp16(uint32_t smem_dst, const void* gsrc) {
    asm volatile("cp.async.cg.shared.global [%0], [%1], 16;" :: "r"(smem_dst), "l"(gsrc));
}
#define CP_COMMIT() asm volatile("cp.async.commit_group;" ::: "memory")
#define CP_WAIT(n)  asm volatile("cp.async.wait_group %0;" :: "n"(n) : "memory")

// ---------------- init ----------------
__global__ void k_init() {
    int t = threadIdx.x;
    g_sum1[t] = 0; g_sq1[t] = 0ULL;
    if (t < N2P) { g_sum2[t] = 0; g_sq2[t] = 0ULL; }
    if (t == 0)  { g_sum3 = 0; g_sq3n = 0; }
}

// ---------------- quantize x: one block per row, 8 elems/thread ----------------
__global__ void k_quant_x(const float* __restrict__ x) {
    int row = blockIdx.x;
    int c   = threadIdx.x;                 // 128 threads, 104 active
    if (c >= KP1 / 8) return;
    int2 o = make_int2(0, 0);
    if (c < IN_F / 8) {                    // 98 full chunks cover all 784
        const float4* p = (const float4*)(x + (size_t)row * IN_F + c * 8);
        float4 v0 = p[0], v1 = p[1];
        int b0 = (int)ternf(fmaf(2.f, v0.x, -1.f));
        int b1 = (int)ternf(fmaf(2.f, v0.y, -1.f));
        int b2 = (int)ternf(fmaf(2.f, v0.z, -1.f));
        int b3 = (int)ternf(fmaf(2.f, v0.w, -1.f));
        int b4 = (int)ternf(fmaf(2.f, v1.x, -1.f));
        int b5 = (int)ternf(fmaf(2.f, v1.y, -1.f));
        int b6 = (int)ternf(fmaf(2.f, v1.z, -1.f));
        int b7 = (int)ternf(fmaf(2.f, v1.w, -1.f));
        o.x = (int)(uint8_t)b0 | ((int)(uint8_t)b1 << 8)
            | ((int)(uint8_t)b2 << 16) | ((int)(uint8_t)b3 << 24);
        o.y = (int)(uint8_t)b4 | ((int)(uint8_t)b5 << 8)
            | ((int)(uint8_t)b6 << 16) | ((int)(uint8_t)b7 << 24);
    }
    *(int2*)&g_A[(size_t)row * KP1 + c * 8] = o;
}

// ---------------- quantize W1 + W2 (merged) ----------------
__global__ void k_quant_w(const float* __restrict__ W1, const float* __restrict__ W2) {
    int idx = blockIdx.x * blockDim.x + threadIdx.x;
    if (idx < HID * KP1) {
        int row = idx / KP1;
        int col = idx - row * KP1;
        int8_t v = 0;
        if (col < IN_F) v = (int8_t)ternf(W1[row * IN_F + col]);
        g_W1q[idx] = v;
    } else {
        int j = idx - HID * KP1;
        if (j >= N2P * HID) return;
        int row = j >> 10;
        int col = j & (HID - 1);
        int8_t v = 0;
        if (row < OUT_F) v = (int8_t)ternf(W2[row * HID + col]);
        g_W2q[j] = v;
    }
}

// ============ GEMM1: [B,832] x [1024,832]^T -> C1 int16 + fused BN1 stats ============
#define G1_STG   4
#define G1_ASZ   (128 * 80)
#define G1_BOFF  (G1_STG * G1_ASZ)
#define G1_SMEM  (2 * G1_STG * G1_ASZ)
#define G1_KT    (KP1 / 64)

__device__ __forceinline__ void g1_load(uint32_t sb, int tid, int bm0, int bn0, int kt) {
    int stage = kt & 3;
    int k0 = kt * 64;
    #pragma unroll
    for (int i = 0; i < 2; i++) {
        int v = tid + i * 256;
        int r = v >> 2, c = (v & 3) * 16;
        cp16(sb + stage * G1_ASZ + r * 80 + c,
             g_A + (size_t)(bm0 + r) * KP1 + k0 + c);
        cp16(sb + G1_BOFF + stage * G1_ASZ + r * 80 + c,
             g_W1q + (size_t)(bn0 + r) * KP1 + k0 + c);
    }
    CP_COMMIT();
}

__global__ void __launch_bounds__(256, 2) k_gemm1(int Bsz) {
    extern __shared__ __align__(16) char smem[];
    const uint32_t sb = smem_u32(smem);
    const int tid = threadIdx.x, warp = tid >> 5, lane = tid & 31;
    const int bm0 = blockIdx.y * 128;
    const int bn0 = blockIdx.x * 128;
    const int wr = warp >> 2, wc = warp & 3;

    const int lr = lane & 7;
    uint32_t abase[4], bbase[2];
    #pragma unroll
    for (int mt = 0; mt < 4; mt++)
        abase[mt] = (uint32_t)((wr * 64 + mt * 16 + ((lane >> 3) & 1) * 8 + lr) * 80
                               + (lane >> 4) * 16);
    #pragma unroll
    for (int np = 0; np < 2; np++)
        bbase[np] = (uint32_t)((wc * 32 + np * 16 + (lane >> 4) * 8 + lr) * 80
                               + ((lane >> 3) & 1) * 16);

    int acc[4][4][4];
    #pragma unroll
    for (int mt = 0; mt < 4; mt++)
        #pragma unroll
        for (int nt = 0; nt < 4; nt++)
            #pragma unroll
            for (int i = 0; i < 4; i++) acc[mt][nt][i] = 0;

    g1_load(sb, tid, bm0, bn0, 0);
    g1_load(sb, tid, bm0, bn0, 1);
    g1_load(sb, tid, bm0, bn0, 2);

    for (int kt = 0; kt < G1_KT; kt++) {
        if (kt < G1_KT - 2)      CP_WAIT(2);
        else if (kt < G1_KT - 1) CP_WAIT(1);
        else                     CP_WAIT(0);
        __syncthreads();
        if (kt + 3 < G1_KT) g1_load(sb, tid, bm0, bn0, kt + 3);

        const uint32_t sa = sb + (kt & 3) * G1_ASZ;
        const uint32_t sbb = sb + G1_BOFF + (kt & 3) * G1_ASZ;
        #pragma unroll
        for (int s = 0; s < 2; s++) {
            uint32_t a[4][4], b[4][2];
            #pragma unroll
            for (int mt = 0; mt < 4; mt++)
                LDSM4(a[mt][0], a[mt][1], a[mt][2], a[mt][3], sa + abase[mt] + s * 32);
            LDSM4(b[0][0], b[0][1], b[1][0], b[1][1], sbb + bbase[0] + s * 32);
            LDSM4(b[2][0], b[2][1], b[3][0], b[3][1], sbb + bbase[1] + s * 32);
            #pragma unroll
            for (int mt = 0; mt < 4; mt++)
                #pragma unroll
                for (int nt = 0; nt < 4; nt++)
                    MMA_S8(acc[mt][nt], a[mt], b[nt]);
        }
    }

    const int g = lane >> 2, q = lane & 3;
    #pragma unroll
    for (int mt = 0; mt < 4; mt++) {
        int row0 = bm0 + wr * 64 + mt * 16 + g;
        #pragma unroll
        for (int nt = 0; nt < 4; nt++) {
            int col = bn0 + wc * 32 + nt * 8 + q * 2;
            short2 lo = make_short2((short)acc[mt][nt][0], (short)acc[mt][nt][1]);
            short2 hi = make_short2((short)acc[mt][nt][2], (short)acc[mt][nt][3]);
            *(short2*)&g_C1[(size_t)row0       * HID + col] = lo;
            *(short2*)&g_C1[(size_t)(row0 + 8) * HID + col] = hi;
        }
    }

    int sums[8], sqs[8];
    #pragma unroll
    for (int nt = 0; nt < 4; nt++)
        #pragma unroll
        for (int c = 0; c < 2; c++) {
            int s_ = 0, q_ = 0;
            #pragma unroll
            for (int mt = 0; mt < 4; mt++) {
                int v1 = acc[mt][nt][c], v2 = acc[mt][nt][c + 2];
                s_ += v1 + v2; q_ += v1 * v1 + v2 * v2;
            }
            sums[nt * 2 + c] = s_; sqs[nt * 2 + c] = q_;
        }
    #pragma unroll
    for (int m = 4; m <= 16; m <<= 1)
        #pragma unroll
        for (int i = 0; i < 8; i++) {
            sums[i] += __shfl_xor_sync(0xffffffffu, sums[i], m);
            sqs[i]  += __shfl_xor_sync(0xffffffffu, sqs[i],  m);
        }
    if (lane < 4) {
        #pragma unroll
        for (int nt = 0; nt < 4; nt++)
            #pragma unroll
            for (int c = 0; c < 2; c++) {
                int col = bn0 + wc * 32 + nt * 8 + lane * 2 + c;
                atomicAdd(&g_sum1[col], sums[nt * 2 + c]);
                atomicAdd(&g_sq1[col],
                          (unsigned long long)(unsigned int)sqs[nt * 2 + c]);
            }
    }
}

// ---------------- BN1 coefs ----------------
__global__ void k_coef1(const float* __restrict__ gamma1,
                        const float* __restrict__ beta1, int Bsz) {
    int f = threadIdx.x;
    double mean = (double)g_sum1[f] / (double)Bsz;
    double var  = (double)g_sq1[f] / (double)Bsz - mean * mean;
    double rstd = 1.0 / sqrt(var + 1e-5);
    double ga = (double)gamma1[f];
    g_a1[f] = (float)(rstd * ga);
    g_b1[f] = (float)((double)beta1[f] - mean * rstd * ga);
}

// ============ GEMM2: fused BN1-apply + ternary + GEMM + fused BN2 stats ============
#define G2_STG    3
#define G2_RSZ    (128 * 144)
#define G2_B2OFF  (G2_STG * G2_RSZ)
#define G2_CAOFF  (G2_B2OFF + 16 * 1040)
#define G2_CBOFF  (G2_CAOFF + 4096)
#define G2_SMEM   (G2_CBOFF + 4096)
#define G2_KT     (HID / 64)

__device__ __forceinline__ void g2_load(uint32_t sb, int tid, int bm0, int kt) {
    int stage = kt % 3;
    #pragma unroll
    for (int i = 0; i < 4; i++) {
        int v = tid + i * 256;
        int r = v >> 3, c = (v & 7) * 16;
        cp16(sb + stage * G2_RSZ + r * 144 + c,
             (const char*)g_C1 + (size_t)(bm0 + r) * 2048 + kt * 128 + c);
    }
    CP_COMMIT();
}

__global__ void __launch_bounds__(256, 2) k_gemm2(int Bsz) {
    extern __shared__ __align__(16) char smem[];
    __shared__ int sS2[16], sQ2[16];
    const uint32_t sb = smem_u32(smem);
    char*  smc = smem;
    float* sCa = (float*)(smem + G2_CAOFF);
    float* sCb = (float*)(smem + G2_CBOFF);
    int8_t* sB2 = (int8_t*)(smem + G2_B2OFF);

    const int tid = threadIdx.x, warp = tid >> 5, lane = tid & 31;
    const int g = lane >> 2, q = lane & 3;
    const int bm0 = blockIdx.x * 128;

    if (tid < 16) { sS2[tid] = 0; sQ2[tid] = 0; }

    #pragma unroll
    for (int i = 0; i < 4; i++) {
        int v = tid + i * 256;
        int r = v >> 6, c = (v & 63) * 16;
        *(int4*)&sB2[r * 1040 + c] = *(const int4*)&g_W2q[r * HID + c];
    }
    ((float4*)sCa)[tid] = ((const float4*)g_a1)[tid];
    ((float4*)sCb)[tid] = ((const float4*)g_b1)[tid];

    int acc[2][4];
    #pragma unroll
    for (int nt = 0; nt < 2; nt++)
        #pragma unroll
        for (int i = 0; i < 4; i++) acc[nt][i] = 0;

    g2_load(sb, tid, bm0, 0);
    g2_load(sb, tid, bm0, 1);

    for (int kt = 0; kt < G2_KT; kt++) {
        if (kt < G2_KT - 1) CP_WAIT(1);
        else                CP_WAIT(0);
        __syncthreads();
        if (kt + 2 < G2_KT) g2_load(sb, tid, bm0, kt + 2);

        const int stage = kt % 3;
        #pragma unroll
        for (int s = 0; s < 2; s++) {
            uint32_t a[4];
            #pragma unroll
            for (int c16 = 0; c16 < 2; c16++)
                #pragma unroll
                for (int h = 0; h < 2; h++) {
                    int row = warp * 16 + g + h * 8;
                    short4 v = *(const short4*)(smc + stage * G2_RSZ + row * 144
                                                + s * 64 + c16 * 32 + q * 8);
                    int f = kt * 64 + s * 32 + c16 * 16 + q * 4;
                    int i0 = (int)ternf(fmaf((float)v.x, sCa[f + 0], sCb[f + 0]));
                    int i1 = (int)ternf(fmaf((float)v.y, sCa[f + 1], sCb[f + 1]));
                    int i2 = (int)ternf(fmaf((float)v.z, sCa[f + 2], sCb[f + 2]));
                    int i3 = (int)ternf(fmaf((float)v.w, sCa[f + 3], sCb[f + 3]));
                    a[h + 2 * c16] = (uint32_t)(uint8_t)i0
                                   | ((uint32_t)(uint8_t)i1 << 8)
                                   | ((uint32_t)(uint8_t)i2 << 16)
                                   | ((uint32_t)(uint8_t)i3 << 24);
                }
            #pragma unroll
            for (int nt = 0; nt < 2; nt++) {
                uint32_t b[2];
                const int8_t* pb = &sB2[(nt * 8 + g) * 1040 + kt * 64 + s * 32 + q * 4];
                b[0] = *(const uint32_t*)(pb);
                b[1] = *(const uint32_t*)(pb + 16);
                MMA_S8(acc[nt], a, b);
            }
        }
    }

    int row0 = bm0 + warp * 16 + g;
    #pragma unroll
    for (int nt = 0; nt < 2; nt++) {
        int col = nt * 8 + q * 2;
        short2 lo = make_short2((short)acc[nt][0], (short)acc[nt][1]);
        short2 hi = make_short2((short)acc[nt][2], (short)acc[nt][3]);
        *(short2*)&g_C2[(size_t)row0       * N2P + col] = lo;
        *(short2*)&g_C2[(size_t)(row0 + 8) * N2P + col] = hi;
    }

    // ---- fused BN2 stats: reduce over warp rows, smem combine, 16 global atomics ----
    #pragma unroll
    for (int nt = 0; nt < 2; nt++)
        #pragma unroll
        for (int c = 0; c < 2; c++) {
            int v1 = acc[nt][c], v2 = acc[nt][c + 2];
            int s_ = v1 + v2;
            int q_ = v1 * v1 + v2 * v2;
            #pragma unroll
            for (int m = 4; m <= 16; m <<= 1) {
                s_ += __shfl_xor_sync(0xffffffffu, s_, m);
                q_ += __shfl_xor_sync(0xffffffffu, q_, m);
            }
            if (lane < 4) {                 // lane == q holder (g==0)
                int col = nt * 8 + lane * 2 + c;
                atomicAdd(&sS2[col], s_);
                atomicAdd(&sQ2[col], q_);   // per-CTA sq <= 128*1024^2 < 2^31
            }
        }
    __syncthreads();
    if (tid < 16) {
        atomicAdd(&g_sum2[tid], sS2[tid]);
        atomicAdd(&g_sq2[tid], (unsigned long long)(unsigned int)sQ2[tid]);
    }
}

// ---------------- BN2 normalize + ternary + tensornorm stats ----------------
__global__ void k_act2(const float* __restrict__ gamma2,
                       const float* __restrict__ beta2, int Bsz) {
    int idx   = blockIdx.x * blockDim.x + threadIdx.x;
    int total = Bsz * OUT_F;
    int s = 0, s2 = 0;
    if (idx < total) {
        int row = idx / OUT_F;
        int col = idx - row * OUT_F;
        int c = g_C2[(size_t)row * N2P + col];
        double mean = (double)g_sum2[col] / (double)Bsz;
        double var  = (double)g_sq2[col] / (double)Bsz - mean * mean;
        double rstd = 1.0 / sqrt(var + 1e-5);
        double z = ((double)c - mean) * rstd * (double)gamma2[col] + (double)beta2[col];
        int ti = (int)fmin(1.0, fmax(-1.0, rint(z)));
        g_T2[idx] = (int8_t)ti;
        s = ti; s2 = ti * ti;
    }
    #pragma unroll
    for (int o = 16; o > 0; o >>= 1) {
        s  += __shfl_xor_sync(0xffffffffu, s,  o);
        s2 += __shfl_xor_sync(0xffffffffu, s2, o);
    }
    if ((threadIdx.x & 31) == 0) {
        atomicAdd(&g_sum3, s);
        atomicAdd(&g_sq3n, s2);
    }
}

// ---------------- TensorNorm ----------------
__global__ void k_final(const float* __restrict__ tn_w,
                        const float* __restrict__ tn_b,
                        float* __restrict__ out, int Bsz) {
    int idx   = blockIdx.x * blockDim.x + threadIdx.x;
    int total = Bsz * OUT_F;
    if (idx >= total) return;
    double N = (double)total;
    double S = (double)g_sum3;
    double m = S / N;
    double var = ((double)g_sq3n - S * S / N) / (N - 1.0);
    double r = 1.0 / sqrt(var + 1e-4);
    out[idx] = (float)(((double)g_T2[idx] - m) * r * (double)tn_w[0] + (double)tn_b[0]);
}

// ---------------- launcher ----------------
extern "C" void kernel_launch(void* const* d_in, const int* in_sizes, int n_in,
                              void* d_out, int out_size) {
    const float* x      = (const float*)d_in[0];
    const float* W1     = (const float*)d_in[1];
    const float* gamma1 = (const float*)d_in[2];
    const float* beta1  = (const float*)d_in[3];
    const float* W2     = (const float*)d_in[4];
    const float* gamma2 = (const float*)d_in[5];
    const float* beta2  = (const float*)d_in[6];
    const float* tn_w   = (const float*)d_in[7];
    const float* tn_b   = (const float*)d_in[8];
    float* out = (float*)d_out;

    int Bsz = in_sizes[0] / IN_F;   // 16384

    cudaFuncSetAttribute(k_gemm1, cudaFuncAttributeMaxDynamicSharedMemorySize, G1_SMEM);
    cudaFuncSetAttribute(k_gemm2, cudaFuncAttributeMaxDynamicSharedMemorySize, G2_SMEM);

    // Launch order matters for ncu capture (-s 5 -c 1, +2 harness offset):
    // our 4th launch (k_gemm1) is the one profiled.
    k_init   <<<1, 1024>>>();
    k_quant_x<<<Bsz, 128>>>(x);
    k_quant_w<<<(HID * KP1 + N2P * HID + 255) / 256, 256>>>(W1, W2);

    dim3 g1(HID / 128, Bsz / 128);
    k_gemm1<<<g1, 256, G1_SMEM>>>(Bsz);            // <- profiled launch

    k_coef1<<<1, 1024>>>(gamma1, beta1, Bsz);
    k_gemm2<<<Bsz / 128, 256, G2_SMEM>>>(Bsz);     // fused BN1-apply + BN2 stats

    k_act2 <<<(Bsz * OUT_F + 255) / 256, 256>>>(gamma2, beta2, Bsz);
    k_final<<<(Bsz * OUT_F + 255) / 256, 256>>>(tn_w, tn_b, out, Bsz);
}

// round 16
// speedup vs baseline: 1.9367x; 1.6158x over previous
#include <cuda_runtime.h>
#include <cuda_fp16.h>
#include <cstdint>

#define IN_F   784
#define KP1    832          // 784 padded to multiple of 64
#define HID    1024
#define OUT_F  10
#define N2P    16
#define B_MAX  16384

// ---------------- device scratch ----------------
__device__ __align__(16) __half  g_Ah [B_MAX * KP1];   // ternary x as f16
__device__ __align__(16) __half  g_W1h[HID   * KP1];   // ternary W1 as f16
__device__ __align__(16) int8_t  g_W2q[N2P   * HID];
__device__ __align__(16) short   g_C1 [B_MAX * HID];
__device__ __align__(16) short   g_C2 [B_MAX * N2P];
__device__ __align__(16) int8_t  g_T2 [B_MAX * OUT_F];

__device__ int                g_sum1[HID];
__device__ unsigned long long g_sq1 [HID];
__device__ __align__(16) float g_a1[HID];
__device__ __align__(16) float g_b1[HID];
__device__ int                g_sum2[N2P];
__device__ unsigned long long g_sq2 [N2P];
__device__ int                g_sum3, g_sq3n;

// ---------------- helpers ----------------
__device__ __forceinline__ float ternf(float v) {
    return fminf(1.f, fmaxf(-1.f, rintf(v)));
}

__device__ __forceinline__ uint32_t smem_u32(const void* p) {
    uint32_t a;
    asm("{ .reg .u64 t; cvta.to.shared.u64 t, %1; cvt.u32.u64 %0, t; }" : "=r"(a) : "l"(p));
    return a;
}

// f16 x f16 -> f32 legacy HMMA (exact for ternary inputs, sums <= 784)
#define MMA_F16(d, a, b)                                                       \
    asm volatile("mma.sync.aligned.m16n8k16.row.col.f32.f16.f16.f32 "          \
        "{%0,%1,%2,%3}, {%4,%5,%6,%7}, {%8,%9}, {%0,%1,%2,%3};"                \
        : "+f"((d)[0]), "+f"((d)[1]), "+f"((d)[2]), "+f"((d)[3])               \
        : "r"((a)[0]), "r"((a)[1]), "r"((a)[2]), "r"((a)[3]),                  \
          "r"((b)[0]), "r"((b)[1]))

#define MMA_S8(d, a, b)                                                        \
    asm volatile("mma.sync.aligned.m16n8k32.row.col.s32.s8.s8.s32 "            \
        "{%0,%1,%2,%3}, {%4,%5,%6,%7}, {%8,%9}, {%0,%1,%2,%3};"                \
        : "+r"((d)[0]), "+r"((d)[1]), "+r"((d)[2]), "+r"((d)[3])               \
        : "r"((a)[0]), "r"((a)[1]), "r"((a)[2]), "r"((a)[3]),                  \
          "r"((b)[0]), "r"((b)[1]))

#define LDSM4(r0, r1, r2, r3, addr)                                            \
    asm volatile("ldmatrix.sync.aligned.m8n8.x4.shared.b16 {%0,%1,%2,%3}, [%4];" \
        : "=r"(r0), "=r"(r1), "=r"(r2), "=r"(r3) : "r"(addr))

__device__ __forceinline__ void cp16(uint32_t smem_dst, const void* gsrc) {
    asm volatile("cp.async.cg.shared.global [%0], [%1], 16;" :: "r"(smem_dst), "l"(gsrc));
}
#define CP_COMMIT() asm volatile("cp.async.commit_group;" ::: "memory")
#define CP_WAIT(n)  asm volatile("cp.async.wait_group %0;" :: "n"(n) : "memory")

// ---------------- init ----------------
__global__ void k_init() {
    int t = threadIdx.x;
    g_sum1[t] = 0; g_sq1[t] = 0ULL;
    if (t < N2P) { g_sum2[t] = 0; g_sq2[t] = 0ULL; }
    if (t == 0)  { g_sum3 = 0; g_sq3n = 0; }
}

// ---------------- quantize x -> f16: one block per row, 8 elems/thread ----------------
__global__ void k_quant_x(const float* __restrict__ x) {
    int row = blockIdx.x;
    int c   = threadIdx.x;                 // 128 threads, 104 active
    if (c >= KP1 / 8) return;
    uint4 o = make_uint4(0, 0, 0, 0);
    if (c < IN_F / 8) {                    // 98 full chunks cover all 784
        const float4* p = (const float4*)(x + (size_t)row * IN_F + c * 8);
        float4 v0 = p[0], v1 = p[1];
        __half2 h0 = __floats2half2_rn(ternf(fmaf(2.f, v0.x, -1.f)),
                                       ternf(fmaf(2.f, v0.y, -1.f)));
        __half2 h1 = __floats2half2_rn(ternf(fmaf(2.f, v0.z, -1.f)),
                                       ternf(fmaf(2.f, v0.w, -1.f)));
        __half2 h2 = __floats2half2_rn(ternf(fmaf(2.f, v1.x, -1.f)),
                                       ternf(fmaf(2.f, v1.y, -1.f)));
        __half2 h3 = __floats2half2_rn(ternf(fmaf(2.f, v1.z, -1.f)),
                                       ternf(fmaf(2.f, v1.w, -1.f)));
        o.x = *(uint32_t*)&h0; o.y = *(uint32_t*)&h1;
        o.z = *(uint32_t*)&h2; o.w = *(uint32_t*)&h3;
    }
    *(uint4*)&g_Ah[(size_t)row * KP1 + c * 8] = o;
}

// ---------------- quantize W1 (f16) + W2 (s8), merged ----------------
__global__ void k_quant_w(const float* __restrict__ W1, const float* __restrict__ W2) {
    int idx = blockIdx.x * blockDim.x + threadIdx.x;
    if (idx < HID * KP1) {
        int row = idx / KP1;
        int col = idx - row * KP1;
        float v = 0.f;
        if (col < IN_F) v = ternf(W1[row * IN_F + col]);
        g_W1h[idx] = __float2half_rn(v);
    } else {
        int j = idx - HID * KP1;
        if (j >= N2P * HID) return;
        int row = j >> 10;
        int col = j & (HID - 1);
        int8_t v = 0;
        if (row < OUT_F) v = (int8_t)ternf(W2[row * HID + col]);
        g_W2q[j] = v;
    }
}

// ============ GEMM1 (HMMA f16): [B,832] x [1024,832]^T -> C1 int16 + BN1 stats ============
// Block 128x128, BK=64 halves (128B rows, pitch 144), 3-stage cp.async,
// ldmatrix b16, 8 warps (2x4) of 64x32, f32 accumulators (exact integers).
#define G1_TS    (128 * 144)        // one A (or B) tile: 18432 B
#define G1_SS    (2 * G1_TS)        // one stage (A+B): 36864 B
#define G1_STG   3
#define G1_SMEM  (G1_STG * G1_SS)   // 110592 B
#define G1_KT    (KP1 / 64)         // 13

__device__ __forceinline__ void g1_load(uint32_t sb, int tid, int bm0, int bn0,
                                        int kt, int stage) {
    int k0 = kt * 64;               // halves
    const char* Abase = (const char*)g_Ah  + ((size_t)bm0 * KP1 + k0) * 2;
    const char* Bbase = (const char*)g_W1h + ((size_t)bn0 * KP1 + k0) * 2;
    #pragma unroll
    for (int i = 0; i < 4; i++) {   // 1024 chunks of 16B per tile
        int v = tid + i * 256;
        int r = v >> 3, c = (v & 7) * 16;
        cp16(sb + stage * G1_SS + r * 144 + c,          Abase + (size_t)r * (KP1 * 2) + c);
        cp16(sb + stage * G1_SS + G1_TS + r * 144 + c,  Bbase + (size_t)r * (KP1 * 2) + c);
    }
    CP_COMMIT();
}

__global__ void __launch_bounds__(256, 2) k_gemm1(int Bsz) {
    extern __shared__ __align__(16) char smem[];
    const uint32_t sb = smem_u32(smem);
    const int tid = threadIdx.x, warp = tid >> 5, lane = tid & 31;
    const int bm0 = blockIdx.y * 128;
    const int bn0 = blockIdx.x * 128;
    const int wr = warp >> 2, wc = warp & 3;

    const int lr = lane & 7;
    uint32_t abase[4], bbase[2];
    #pragma unroll
    for (int mt = 0; mt < 4; mt++)
        abase[mt] = (uint32_t)((wr * 64 + mt * 16 + ((lane >> 3) & 1) * 8 + lr) * 144
                               + (lane >> 4) * 16);
    #pragma unroll
    for (int np = 0; np < 2; np++)
        bbase[np] = (uint32_t)((wc * 32 + np * 16 + (lane >> 4) * 8 + lr) * 144
                               + ((lane >> 3) & 1) * 16);

    float facc[4][4][4];
    #pragma unroll
    for (int mt = 0; mt < 4; mt++)
        #pragma unroll
        for (int nt = 0; nt < 4; nt++)
            #pragma unroll
            for (int i = 0; i < 4; i++) facc[mt][nt][i] = 0.f;

    g1_load(sb, tid, bm0, bn0, 0, 0);
    g1_load(sb, tid, bm0, bn0, 1, 1);

    int st = 0;                      // stage of current kt
    for (int kt = 0; kt < G1_KT; kt++) {
        if (kt + 2 < G1_KT) CP_WAIT(1);
        else                CP_WAIT(0);
        __syncthreads();
        int st2 = st + 2 >= 3 ? st - 1 : st + 2;    // (st+2) % 3
        if (kt + 2 < G1_KT) g1_load(sb, tid, bm0, bn0, kt + 2, st2);

        const uint32_t sa  = sb + st * G1_SS;
        const uint32_t sbb = sa + G1_TS;
        #pragma unroll
        for (int s = 0; s < 4; s++) {               // 4 x K=16 per 64-half chunk
            uint32_t a[4][4], b[4][2];
            #pragma unroll
            for (int mt = 0; mt < 4; mt++)
                LDSM4(a[mt][0], a[mt][1], a[mt][2], a[mt][3], sa + abase[mt] + s * 32);
            LDSM4(b[0][0], b[0][1], b[1][0], b[1][1], sbb + bbase[0] + s * 32);
            LDSM4(b[2][0], b[2][1], b[3][0], b[3][1], sbb + bbase[1] + s * 32);
            #pragma unroll
            for (int mt = 0; mt < 4; mt++)
                #pragma unroll
                for (int nt = 0; nt < 4; nt++)
                    MMA_F16(facc[mt][nt], a[mt], b[nt]);
        }
        st = st + 1 >= 3 ? 0 : st + 1;
    }

    // exact f32 -> int conversion (all values are integers, |v| <= 784)
    int acc[4][4][4];
    #pragma unroll
    for (int mt = 0; mt < 4; mt++)
        #pragma unroll
        for (int nt = 0; nt < 4; nt++)
            #pragma unroll
            for (int i = 0; i < 4; i++)
                acc[mt][nt][i] = __float2int_rn(facc[mt][nt][i]);

    const int g = lane >> 2, q = lane & 3;
    #pragma unroll
    for (int mt = 0; mt < 4; mt++) {
        int row0 = bm0 + wr * 64 + mt * 16 + g;
        #pragma unroll
        for (int nt = 0; nt < 4; nt++) {
            int col = bn0 + wc * 32 + nt * 8 + q * 2;
            short2 lo = make_short2((short)acc[mt][nt][0], (short)acc[mt][nt][1]);
            short2 hi = make_short2((short)acc[mt][nt][2], (short)acc[mt][nt][3]);
            *(short2*)&g_C1[(size_t)row0       * HID + col] = lo;
            *(short2*)&g_C1[(size_t)(row0 + 8) * HID + col] = hi;
        }
    }

    int sums[8], sqs[8];
    #pragma unroll
    for (int nt = 0; nt < 4; nt++)
        #pragma unroll
        for (int c = 0; c < 2; c++) {
            int s_ = 0, q_ = 0;
            #pragma unroll
            for (int mt = 0; mt < 4; mt++) {
                int v1 = acc[mt][nt][c], v2 = acc[mt][nt][c + 2];
                s_ += v1 + v2; q_ += v1 * v1 + v2 * v2;
            }
            sums[nt * 2 + c] = s_; sqs[nt * 2 + c] = q_;
        }
    #pragma unroll
    for (int m = 4; m <= 16; m <<= 1)
        #pragma unroll
        for (int i = 0; i < 8; i++) {
            sums[i] += __shfl_xor_sync(0xffffffffu, sums[i], m);
            sqs[i]  += __shfl_xor_sync(0xffffffffu, sqs[i],  m);
        }
    if (lane < 4) {
        #pragma unroll
        for (int nt = 0; nt < 4; nt++)
            #pragma unroll
            for (int c = 0; c < 2; c++) {
                int col = bn0 + wc * 32 + nt * 8 + lane * 2 + c;
                atomicAdd(&g_sum1[col], sums[nt * 2 + c]);
                atomicAdd(&g_sq1[col],
                          (unsigned long long)(unsigned int)sqs[nt * 2 + c]);
            }
    }
}

// ---------------- BN1 coefs ----------------
__global__ void k_coef1(const float* __restrict__ gamma1,
                        const float* __restrict__ beta1, int Bsz) {
    int f = threadIdx.x;
    double mean = (double)g_sum1[f] / (double)Bsz;
    double var  = (double)g_sq1[f] / (double)Bsz - mean * mean;
    double rstd = 1.0 / sqrt(var + 1e-5);
    double ga = (double)gamma1[f];
    g_a1[f] = (float)(rstd * ga);
    g_b1[f] = (float)((double)beta1[f] - mean * rstd * ga);
}

// ============ GEMM2: fused BN1-apply + ternary + GEMM (IMMA) + fused BN2 stats ============
#define G2_STG    3
#define G2_RSZ    (128 * 144)
#define G2_B2OFF  (G2_STG * G2_RSZ)
#define G2_CAOFF  (G2_B2OFF + 16 * 1040)
#define G2_CBOFF  (G2_CAOFF + 4096)
#define G2_SMEM   (G2_CBOFF + 4096)
#define G2_KT     (HID / 64)

__device__ __forceinline__ void g2_load(uint32_t sb, int tid, int bm0, int kt) {
    int stage = kt % 3;
    #pragma unroll
    for (int i = 0; i < 4; i++) {
        int v = tid + i * 256;
        int r = v >> 3, c = (v & 7) * 16;
        cp16(sb + stage * G2_RSZ + r * 144 + c,
             (const char*)g_C1 + (size_t)(bm0 + r) * 2048 + kt * 128 + c);
    }
    CP_COMMIT();
}

__global__ void __launch_bounds__(256, 2) k_gemm2(int Bsz) {
    extern __shared__ __align__(16) char smem[];
    __shared__ int sS2[16], sQ2[16];
    const uint32_t sb = smem_u32(smem);
    char*  smc = smem;
    float* sCa = (float*)(smem + G2_CAOFF);
    float* sCb = (float*)(smem + G2_CBOFF);
    int8_t* sB2 = (int8_t*)(smem + G2_B2OFF);

    const int tid = threadIdx.x, warp = tid >> 5, lane = tid & 31;
    const int g = lane >> 2, q = lane & 3;
    const int bm0 = blockIdx.x * 128;

    if (tid < 16) { sS2[tid] = 0; sQ2[tid] = 0; }

    #pragma unroll
    for (int i = 0; i < 4; i++) {
        int v = tid + i * 256;
        int r = v >> 6, c = (v & 63) * 16;
        *(int4*)&sB2[r * 1040 + c] = *(const int4*)&g_W2q[r * HID + c];
    }
    ((float4*)sCa)[tid] = ((const float4*)g_a1)[tid];
    ((float4*)sCb)[tid] = ((const float4*)g_b1)[tid];

    int acc[2][4];
    #pragma unroll
    for (int nt = 0; nt < 2; nt++)
        #pragma unroll
        for (int i = 0; i < 4; i++) acc[nt][i] = 0;

    g2_load(sb, tid, bm0, 0);
    g2_load(sb, tid, bm0, 1);

    for (int kt = 0; kt < G2_KT; kt++) {
        if (kt < G2_KT - 1) CP_WAIT(1);
        else                CP_WAIT(0);
        __syncthreads();
        if (kt + 2 < G2_KT) g2_load(sb, tid, bm0, kt + 2);

        const int stage = kt % 3;
        #pragma unroll
        for (int s = 0; s < 2; s++) {
            uint32_t a[4];
            #pragma unroll
            for (int c16 = 0; c16 < 2; c16++)
                #pragma unroll
                for (int h = 0; h < 2; h++) {
                    int row = warp * 16 + g + h * 8;
                    short4 v = *(const short4*)(smc + stage * G2_RSZ + row * 144
                                                + s * 64 + c16 * 32 + q * 8);
                    int f = kt * 64 + s * 32 + c16 * 16 + q * 4;
                    int i0 = (int)ternf(fmaf((float)v.x, sCa[f + 0], sCb[f + 0]));
                    int i1 = (int)ternf(fmaf((float)v.y, sCa[f + 1], sCb[f + 1]));
                    int i2 = (int)ternf(fmaf((float)v.z, sCa[f + 2], sCb[f + 2]));
                    int i3 = (int)ternf(fmaf((float)v.w, sCa[f + 3], sCb[f + 3]));
                    a[h + 2 * c16] = (uint32_t)(uint8_t)i0
                                   | ((uint32_t)(uint8_t)i1 << 8)
                                   | ((uint32_t)(uint8_t)i2 << 16)
                                   | ((uint32_t)(uint8_t)i3 << 24);
                }
            #pragma unroll
            for (int nt = 0; nt < 2; nt++) {
                uint32_t b[2];
                const int8_t* pb = &sB2[(nt * 8 + g) * 1040 + kt * 64 + s * 32 + q * 4];
                b[0] = *(const uint32_t*)(pb);
                b[1] = *(const uint32_t*)(pb + 16);
                MMA_S8(acc[nt], a, b);
            }
        }
    }

    int row0 = bm0 + warp * 16 + g;
    #pragma unroll
    for (int nt = 0; nt < 2; nt++) {
        int col = nt * 8 + q * 2;
        short2 lo = make_short2((short)acc[nt][0], (short)acc[nt][1]);
        short2 hi = make_short2((short)acc[nt][2], (short)acc[nt][3]);
        *(short2*)&g_C2[(size_t)row0       * N2P + col] = lo;
        *(short2*)&g_C2[(size_t)(row0 + 8) * N2P + col] = hi;
    }

    // ---- fused BN2 stats ----
    #pragma unroll
    for (int nt = 0; nt < 2; nt++)
        #pragma unroll
        for (int c = 0; c < 2; c++) {
            int v1 = acc[nt][c], v2 = acc[nt][c + 2];
            int s_ = v1 + v2;
            int q_ = v1 * v1 + v2 * v2;
            #pragma unroll
            for (int m = 4; m <= 16; m <<= 1) {
                s_ += __shfl_xor_sync(0xffffffffu, s_, m);
                q_ += __shfl_xor_sync(0xffffffffu, q_, m);
            }
            if (lane < 4) {
                int col = nt * 8 + lane * 2 + c;
                atomicAdd(&sS2[col], s_);
                atomicAdd(&sQ2[col], q_);
            }
        }
    __syncthreads();
    if (tid < 16) {
        atomicAdd(&g_sum2[tid], sS2[tid]);
        atomicAdd(&g_sq2[tid], (unsigned long long)(unsigned int)sQ2[tid]);
    }
}

// ---------------- BN2 normalize + ternary + tensornorm stats ----------------
__global__ void k_act2(const float* __restrict__ gamma2,
                       const float* __restrict__ beta2, int Bsz) {
    int idx   = blockIdx.x * blockDim.x + threadIdx.x;
    int total = Bsz * OUT_F;
    int s = 0, s2 = 0;
    if (idx < total) {
        int row = idx / OUT_F;
        int col = idx - row * OUT_F;
        int c = g_C2[(size_t)row * N2P + col];
        double mean = (double)g_sum2[col] / (double)Bsz;
        double var  = (double)g_sq2[col] / (double)Bsz - mean * mean;
        double rstd = 1.0 / sqrt(var + 1e-5);
        double z = ((double)c - mean) * rstd * (double)gamma2[col] + (double)beta2[col];
        int ti = (int)fmin(1.0, fmax(-1.0, rint(z)));
        g_T2[idx] = (int8_t)ti;
        s = ti; s2 = ti * ti;
    }
    #pragma unroll
    for (int o = 16; o > 0; o >>= 1) {
        s  += __shfl_xor_sync(0xffffffffu, s,  o);
        s2 += __shfl_xor_sync(0xffffffffu, s2, o);
    }
    if ((threadIdx.x & 31) == 0) {
        atomicAdd(&g_sum3, s);
        atomicAdd(&g_sq3n, s2);
    }
}

// ---------------- TensorNorm ----------------
__global__ void k_final(const float* __restrict__ tn_w,
                        const float* __restrict__ tn_b,
                        float* __restrict__ out, int Bsz) {
    int idx   = blockIdx.x * blockDim.x + threadIdx.x;
    int total = Bsz * OUT_F;
    if (idx >= total) return;
    double N = (double)total;
    double S = (double)g_sum3;
    double m = S / N;
    double var = ((double)g_sq3n - S * S / N) / (N - 1.0);
    double r = 1.0 / sqrt(var + 1e-4);
    out[idx] = (float)(((double)g_T2[idx] - m) * r * (double)tn_w[0] + (double)tn_b[0]);
}

// ---------------- launcher ----------------
extern "C" void kernel_launch(void* const* d_in, const int* in_sizes, int n_in,
                              void* d_out, int out_size) {
    const float* x      = (const float*)d_in[0];
    const float* W1     = (const float*)d_in[1];
    const float* gamma1 = (const float*)d_in[2];
    const float* beta1  = (const float*)d_in[3];
    const float* W2     = (const float*)d_in[4];
    const float* gamma2 = (const float*)d_in[5];
    const float* beta2  = (const float*)d_in[6];
    const float* tn_w   = (const float*)d_in[7];
    const float* tn_b   = (const float*)d_in[8];
    float* out = (float*)d_out;

    int Bsz = in_sizes[0] / IN_F;   // 16384

    cudaFuncSetAttribute(k_gemm1, cudaFuncAttributeMaxDynamicSharedMemorySize, G1_SMEM);
    cudaFuncSetAttribute(k_gemm2, cudaFuncAttributeMaxDynamicSharedMemorySize, G2_SMEM);

    // k_gemm1 stays our 4th launch = the stable ncu capture slot.
    k_init   <<<1, 1024>>>();
    k_quant_x<<<Bsz, 128>>>(x);
    k_quant_w<<<(HID * KP1 + N2P * HID + 255) / 256, 256>>>(W1, W2);

    dim3 g1(HID / 128, Bsz / 128);
    k_gemm1<<<g1, 256, G1_SMEM>>>(Bsz);            // <- profiled (HMMA experiment)

    k_coef1<<<1, 1024>>>(gamma1, beta1, Bsz);
    k_gemm2<<<Bsz / 128, 256, G2_SMEM>>>(Bsz);

    k_act2 <<<(Bsz * OUT_F + 255) / 256, 256>>>(gamma2, beta2, Bsz);
    k_final<<<(Bsz * OUT_F + 255) / 256, 256>>>(tn_w, tn_b, out, Bsz);
}